// round 8
// baseline (speedup 1.0000x reference)
#include <cuda_runtime.h>
#include <cuda_fp16.h>
#include <cstdint>

#define N_NODES   50000
#define F_DIM     256
#define N_EDGES   800000
#define PAD_M     50048          // 391 * 128

#define SCAN_B    256
#define SCAN_NB   ((N_NODES + SCAN_B - 1) / SCAN_B)   // 196

// Launch A roles
#define HIST_B    3125                      // ceil(800000/256)
#define PREPW_B   64
#define PREPX_B   6250                      // 50000*256/8/256
#define F1_BLOCKS (HIST_B + PREPW_B + PREPX_B)

// Launch C roles: scatter first (drains fast), then GEMM
#define SCAT_B    3125                      // ceil(800000/256)
#define GEMM_B    782                       // (PAD_M/128) * (256/128)
#define F2_BLOCKS (SCAT_B + GEMM_B)

// Scratch (__device__ globals; no allocation allowed)
__device__ __half g_yh[(size_t)N_NODES * F_DIM];  // Y = X @ W^T, fp16
__device__ __half g_xh[(size_t)N_NODES * F_DIM];  // X in fp16
__device__ __half g_wh[F_DIM * F_DIM];            // W in fp16
__device__ int    g_cnt[N_NODES];
__device__ int    g_off[N_NODES + 1];
__device__ int    g_pos[N_NODES];
__device__ unsigned long long g_scan_pkt[SCAN_NB];
__device__ int2   g_cv[N_EDGES];                  // packed (col, val-bits)

// ---------------------------------------------------------------------------
// Fused launch A: hist | prep_w | prep_x   (independent roles)
// ---------------------------------------------------------------------------
__global__ __launch_bounds__(256)
void k_fused_a(const int*   __restrict__ edge_row,
               const float* __restrict__ W,
               const float* __restrict__ X) {
    int bid = blockIdx.x;
    int tid = threadIdx.x;
    if (bid < HIST_B) {
        int e = bid * 256 + tid;
        if (e < N_EDGES) atomicAdd(&g_cnt[edge_row[e]], 1);
    } else if (bid < HIST_B + PREPW_B) {
        int i = (bid - HIST_B) * 256 + tid;          // float4 index, 16384 total
        float4 v = reinterpret_cast<const float4*>(W)[i];
        __half2 h0 = __floats2half2_rn(v.x, v.y);
        __half2 h1 = __floats2half2_rn(v.z, v.w);
        reinterpret_cast<__half2*>(g_wh)[2 * i]     = h0;
        reinterpret_cast<__half2*>(g_wh)[2 * i + 1] = h1;
    } else {
        int i = (bid - HIST_B - PREPW_B) * 256 + tid;   // 8-half chunk index
        const float4* xp = reinterpret_cast<const float4*>(X) + 2 * (size_t)i;
        float4 v0 = __ldg(xp);
        float4 v1 = __ldg(xp + 1);
        __half2 h0 = __floats2half2_rn(v0.x, v0.y);
        __half2 h1 = __floats2half2_rn(v0.z, v0.w);
        __half2 h2 = __floats2half2_rn(v1.x, v1.y);
        __half2 h3 = __floats2half2_rn(v1.z, v1.w);
        uint4 u;
        u.x = *reinterpret_cast<uint32_t*>(&h0);
        u.y = *reinterpret_cast<uint32_t*>(&h1);
        u.z = *reinterpret_cast<uint32_t*>(&h2);
        u.w = *reinterpret_cast<uint32_t*>(&h3);
        reinterpret_cast<uint4*>(g_xh)[i] = u;
    }
}

// ---------------------------------------------------------------------------
// Single-pass decoupled-lookback scan
// ---------------------------------------------------------------------------
__global__ void k_scan_fused() {
    __shared__ int warp_sums[8];
    __shared__ int s_base;
    const int b    = blockIdx.x;
    const int t    = threadIdx.x;
    const int lane = t & 31;
    const int w    = t >> 5;
    const int i    = b * SCAN_B + t;

    int v = (i < N_NODES) ? g_cnt[i] : 0;

    int inc = v;
#pragma unroll
    for (int d = 1; d < 32; d <<= 1) {
        int tt = __shfl_up_sync(0xffffffffu, inc, d);
        if (lane >= d) inc += tt;
    }
    if (lane == 31) warp_sums[w] = inc;
    __syncthreads();
    if (w == 0) {
        int ws = (lane < 8) ? warp_sums[lane] : 0;
#pragma unroll
        for (int d = 1; d < 8; d <<= 1) {
            int tt = __shfl_up_sync(0xffffffffu, ws, d);
            if (lane >= d) ws += tt;
        }
        if (lane < 8) warp_sums[lane] = ws;
    }
    __syncthreads();
    int excl  = inc - v + ((w > 0) ? warp_sums[w - 1] : 0);
    int total = warp_sums[7];

    if (t == 0) {
        if (b == 0) {
            atomicExch(&g_scan_pkt[0], (2ULL << 62) | (unsigned)total);
            s_base = 0;
        } else {
            atomicExch(&g_scan_pkt[b], (1ULL << 62) | (unsigned)total);
            int run = 0;
            int j = b - 1;
            while (true) {
                unsigned long long p;
                while (((p = atomicAdd(&g_scan_pkt[j], 0ULL)) >> 62) == 0) {}
                run += (int)(p & 0xFFFFFFFFULL);
                if ((p >> 62) == 2ULL) break;
                j--;
            }
            atomicExch(&g_scan_pkt[b], (2ULL << 62) | (unsigned)(run + total));
            s_base = run;
        }
    }
    __syncthreads();
    int base = s_base;
    if (i < N_NODES) {
        int o = base + excl;
        g_off[i] = o;
        g_pos[i] = o;
    }
    if (i == N_NODES - 1) g_off[N_NODES] = N_EDGES;
}

// ---------------------------------------------------------------------------
// Fused launch C: scatter (blocks [0, SCAT_B)) | gemm (rest)
// GEMM: R6-proven shape. CTA 128x128, BK=32, 8 warps 4(M) x 2(N), 256 thr,
// 2 CTAs/SM. A/W tiles are plain 16B fp16 copies (pre-converted).
// ---------------------------------------------------------------------------
#define BM 128
#define BN 128
#define BK 32
#define LDS_K 40

__device__ __forceinline__ void mma_f16(float* c, const uint32_t* a, const uint32_t* b) {
    asm volatile(
        "mma.sync.aligned.m16n8k16.row.col.f32.f16.f16.f32 "
        "{%0,%1,%2,%3}, {%4,%5,%6,%7}, {%8,%9}, {%0,%1,%2,%3};"
        : "+f"(c[0]), "+f"(c[1]), "+f"(c[2]), "+f"(c[3])
        : "r"(a[0]), "r"(a[1]), "r"(a[2]), "r"(a[3]), "r"(b[0]), "r"(b[1]));
}

__global__ __launch_bounds__(256, 2)
void k_fused_c(const int*   __restrict__ edge_row,
               const int*   __restrict__ edge_col,
               const float* __restrict__ edge_val) {
    __shared__ __half As[BM][LDS_K];   // 10 KB
    __shared__ __half Ws[BN][LDS_K];   // 10 KB

    const int bid = blockIdx.x;
    const int t   = threadIdx.x;

    if (bid < SCAT_B) {
        // -------- scatter role --------
        int e = bid * 256 + t;
        if (e < N_EDGES) {
            int r = edge_row[e];
            int p = atomicAdd(&g_pos[r], 1);
            g_cv[p] = make_int2(edge_col[e], __float_as_int(edge_val[e]));
        }
        return;
    }

    // -------- GEMM role --------
    const int gb   = bid - SCAT_B;     // 0..781
    const int m0   = (gb >> 1) * BM;
    const int n0   = (gb & 1) * BN;
    const int lane = t & 31;
    const int wid  = t >> 5;           // 0..7
    const int wm   = wid & 3;          // 4 warps along M
    const int wn   = wid >> 2;         // 2 warps along N
    const int g    = lane >> 2;
    const int tid4 = lane & 3;

    float acc[2][8][4];
#pragma unroll
    for (int i = 0; i < 2; i++)
#pragma unroll
        for (int j = 0; j < 8; j++)
#pragma unroll
            for (int k = 0; k < 4; k++) acc[i][j][k] = 0.f;

    for (int k0 = 0; k0 < F_DIM; k0 += BK) {
        // stage A: 128 rows x 32 halfs = 512 uint4, 2 per thread
#pragma unroll
        for (int i = 0; i < 2; i++) {
            int idx = t + i * 256;
            int row = idx >> 2;        // 0..127
            int c8  = idx & 3;         // 0..3
            int m   = m0 + row;
            uint4 u = make_uint4(0, 0, 0, 0);
            if (m < N_NODES)
                u = *reinterpret_cast<const uint4*>(g_xh + (size_t)m * F_DIM + k0 + c8 * 8);
            *reinterpret_cast<uint4*>(&As[row][c8 * 8]) = u;
        }
        // stage W: 128 rows x 32 halfs = 512 uint4, 2 per thread
#pragma unroll
        for (int i = 0; i < 2; i++) {
            int idx = t + i * 256;
            int row = idx >> 2;
            int c8  = idx & 3;
            uint4 u = *reinterpret_cast<const uint4*>(
                g_wh + (size_t)(n0 + row) * F_DIM + k0 + c8 * 8);
            *reinterpret_cast<uint4*>(&Ws[row][c8 * 8]) = u;
        }
        __syncthreads();

#pragma unroll
        for (int ks = 0; ks < 2; ks++) {
            int kb = ks * 16;
            uint32_t a[2][4];
#pragma unroll
            for (int mi = 0; mi < 2; mi++) {
                int r = wm * 32 + mi * 16;
                a[mi][0] = *reinterpret_cast<const uint32_t*>(&As[r + g    ][kb + 2 * tid4]);
                a[mi][1] = *reinterpret_cast<const uint32_t*>(&As[r + g + 8][kb + 2 * tid4]);
                a[mi][2] = *reinterpret_cast<const uint32_t*>(&As[r + g    ][kb + 2 * tid4 + 8]);
                a[mi][3] = *reinterpret_cast<const uint32_t*>(&As[r + g + 8][kb + 2 * tid4 + 8]);
            }
            uint32_t b[8][2];
#pragma unroll
            for (int ni = 0; ni < 8; ni++) {
                int n = wn * 64 + ni * 8 + g;
                b[ni][0] = *reinterpret_cast<const uint32_t*>(&Ws[n][kb + 2 * tid4]);
                b[ni][1] = *reinterpret_cast<const uint32_t*>(&Ws[n][kb + 2 * tid4 + 8]);
            }
#pragma unroll
            for (int mi = 0; mi < 2; mi++)
#pragma unroll
                for (int ni = 0; ni < 8; ni++)
                    mma_f16(acc[mi][ni], a[mi], b[ni]);
        }
        __syncthreads();
    }

    // store Y as fp16
#pragma unroll
    for (int mi = 0; mi < 2; mi++) {
        int r_base = m0 + wm * 32 + mi * 16;
#pragma unroll
        for (int ni = 0; ni < 8; ni++) {
            int col = n0 + wn * 64 + ni * 8 + 2 * tid4;
            int r0 = r_base + g;
            int r1 = r_base + g + 8;
            if (r0 < N_NODES) {
                __half2 h = __floats2half2_rn(acc[mi][ni][0], acc[mi][ni][1]);
                *reinterpret_cast<__half2*>(g_yh + (size_t)r0 * F_DIM + col) = h;
            }
            if (r1 < N_NODES) {
                __half2 h = __floats2half2_rn(acc[mi][ni][2], acc[mi][ni][3]);
                *reinterpret_cast<__half2*>(g_yh + (size_t)r1 * F_DIM + col) = h;
            }
        }
    }
}

// ---------------------------------------------------------------------------
// Gather: out[r] = sum_e val_e * Y[col_e] + b.  One warp per row.
// launch_bounds(256, 6): cap regs to raise occupancy (was 43 regs / ~50% occ).
// ---------------------------------------------------------------------------
__device__ __forceinline__ void fma8(float* acc, uint4 u, float v) {
    const __half2* h = reinterpret_cast<const __half2*>(&u);
#pragma unroll
    for (int q = 0; q < 4; q++) {
        float2 f = __half22float2(h[q]);
        acc[2 * q]     += v * f.x;
        acc[2 * q + 1] += v * f.y;
    }
}

__global__ __launch_bounds__(256, 6)
void k_gather(const float* __restrict__ bias, float* __restrict__ out) {
    int r    = (blockIdx.x * blockDim.x + threadIdx.x) >> 5;
    int lane = threadIdx.x & 31;
    if (r >= N_NODES) return;

    float acc[8];
#pragma unroll
    for (int q = 0; q < 8; q++) acc[q] = 0.f;

    int start = g_off[r];
    int end   = g_off[r + 1];

    for (int base = start; base < end; base += 32) {
        int n = min(32, end - base);
        int   col = 0;
        float val = 0.f;
        if (lane < n) {
            int2 cv = __ldg(&g_cv[base + lane]);
            col = cv.x;
            val = __int_as_float(cv.y);
        }
        int j = 0;
        for (; j + 4 <= n; j += 4) {
            int   c0 = __shfl_sync(0xffffffffu, col, j);
            int   c1 = __shfl_sync(0xffffffffu, col, j + 1);
            int   c2 = __shfl_sync(0xffffffffu, col, j + 2);
            int   c3 = __shfl_sync(0xffffffffu, col, j + 3);
            float v0 = __shfl_sync(0xffffffffu, val, j);
            float v1 = __shfl_sync(0xffffffffu, val, j + 1);
            float v2 = __shfl_sync(0xffffffffu, val, j + 2);
            float v3 = __shfl_sync(0xffffffffu, val, j + 3);
            uint4 u0 = __ldg(reinterpret_cast<const uint4*>(g_yh + (size_t)c0 * F_DIM) + lane);
            uint4 u1 = __ldg(reinterpret_cast<const uint4*>(g_yh + (size_t)c1 * F_DIM) + lane);
            uint4 u2 = __ldg(reinterpret_cast<const uint4*>(g_yh + (size_t)c2 * F_DIM) + lane);
            uint4 u3 = __ldg(reinterpret_cast<const uint4*>(g_yh + (size_t)c3 * F_DIM) + lane);
            fma8(acc, u0, v0);
            fma8(acc, u1, v1);
            fma8(acc, u2, v2);
            fma8(acc, u3, v3);
        }
        for (; j < n; j++) {
            int   c = __shfl_sync(0xffffffffu, col, j);
            float v = __shfl_sync(0xffffffffu, val, j);
            uint4 u = __ldg(reinterpret_cast<const uint4*>(g_yh + (size_t)c * F_DIM) + lane);
            fma8(acc, u, v);
        }
    }

    const float4* bp = reinterpret_cast<const float4*>(bias + lane * 8);
    float4 b0 = __ldg(bp);
    float4 b1 = __ldg(bp + 1);
    float4 o0 = make_float4(acc[0] + b0.x, acc[1] + b0.y, acc[2] + b0.z, acc[3] + b0.w);
    float4 o1 = make_float4(acc[4] + b1.x, acc[5] + b1.y, acc[6] + b1.z, acc[7] + b1.w);
    float4* orow = reinterpret_cast<float4*>(out + (size_t)r * F_DIM + lane * 8);
    orow[0] = o0;
    orow[1] = o1;
}

// ---------------------------------------------------------------------------
// Launch
// ---------------------------------------------------------------------------
extern "C" void kernel_launch(void* const* d_in, const int* in_sizes, int n_in,
                              void* d_out, int out_size) {
    const float* x        = (const float*)d_in[0];
    const int*   edge_row = (const int*)  d_in[1];
    const int*   edge_col = (const int*)  d_in[2];
    const float* edge_val = (const float*)d_in[3];
    const float* W        = (const float*)d_in[4];
    const float* b        = (const float*)d_in[5];
    float*       out      = (float*)d_out;

    void* cnt_ptr = nullptr;
    cudaGetSymbolAddress(&cnt_ptr, g_cnt);
    cudaMemsetAsync(cnt_ptr, 0, N_NODES * sizeof(int));
    void* pkt_ptr = nullptr;
    cudaGetSymbolAddress(&pkt_ptr, g_scan_pkt);
    cudaMemsetAsync(pkt_ptr, 0, SCAN_NB * sizeof(unsigned long long));

    // A: hist | prep_w | prep_x
    k_fused_a<<<F1_BLOCKS, 256>>>(edge_row, W, x);
    // B: scan (needs hist)
    k_scan_fused<<<SCAN_NB, SCAN_B>>>();
    // C: scatter (needs scan) | gemm (needs prep_w/prep_x)
    k_fused_c<<<F2_BLOCKS, 256>>>(edge_row, edge_col, edge_val);
    // D: gather (needs gemm + scatter)
    k_gather<<<(N_NODES * 32 + 255) / 256, 256>>>(b, out);
}

// round 9
// speedup vs baseline: 1.0724x; 1.0724x over previous
#include <cuda_runtime.h>
#include <cuda_fp16.h>
#include <cstdint>

#define N_NODES   50000
#define F_DIM     256
#define N_EDGES   800000
#define PAD_M     50048          // 391 * 128

#define SCAN_B    256
#define SCAN_NB   ((N_NODES + SCAN_B - 1) / SCAN_B)   // 196

// Launch A roles: hist (+rank) | prep_w
#define HIST_B    3125                      // ceil(800000/256)
#define PREPW_B   64
#define F1_BLOCKS (HIST_B + PREPW_B)

// Scratch (__device__ globals; no allocation allowed)
__device__ __half g_yh[(size_t)N_NODES * F_DIM];  // Y = X @ W^T, fp16
__device__ __half g_wh[F_DIM * F_DIM];            // W in fp16
__device__ int    g_cnt[N_NODES];
__device__ int    g_off[N_NODES + 1];
__device__ int    g_rank[N_EDGES];                // edge rank within its row
__device__ unsigned long long g_scan_pkt[SCAN_NB];
__device__ int2   g_cv[N_EDGES];                  // packed (col, val-bits)

// ---------------------------------------------------------------------------
// Fused launch A: hist (stores per-edge rank) | prep_w
// ---------------------------------------------------------------------------
__global__ __launch_bounds__(256)
void k_fused_a(const int*   __restrict__ edge_row,
               const float* __restrict__ W) {
    int bid = blockIdx.x;
    int tid = threadIdx.x;
    if (bid < HIST_B) {
        int e = bid * 256 + tid;
        if (e < N_EDGES) {
            int r = edge_row[e];
            g_rank[e] = atomicAdd(&g_cnt[r], 1);   // rank within row
        }
    } else {
        int i = (bid - HIST_B) * 256 + tid;        // float4 index, 16384 total
        float4 v = reinterpret_cast<const float4*>(W)[i];
        __half2 h0 = __floats2half2_rn(v.x, v.y);
        __half2 h1 = __floats2half2_rn(v.z, v.w);
        reinterpret_cast<__half2*>(g_wh)[2 * i]     = h0;
        reinterpret_cast<__half2*>(g_wh)[2 * i + 1] = h1;
    }
}

// ---------------------------------------------------------------------------
// Single-pass decoupled-lookback scan
// ---------------------------------------------------------------------------
__global__ void k_scan_fused() {
    __shared__ int warp_sums[8];
    __shared__ int s_base;
    const int b    = blockIdx.x;
    const int t    = threadIdx.x;
    const int lane = t & 31;
    const int w    = t >> 5;
    const int i    = b * SCAN_B + t;

    int v = (i < N_NODES) ? g_cnt[i] : 0;

    int inc = v;
#pragma unroll
    for (int d = 1; d < 32; d <<= 1) {
        int tt = __shfl_up_sync(0xffffffffu, inc, d);
        if (lane >= d) inc += tt;
    }
    if (lane == 31) warp_sums[w] = inc;
    __syncthreads();
    if (w == 0) {
        int ws = (lane < 8) ? warp_sums[lane] : 0;
#pragma unroll
        for (int d = 1; d < 8; d <<= 1) {
            int tt = __shfl_up_sync(0xffffffffu, ws, d);
            if (lane >= d) ws += tt;
        }
        if (lane < 8) warp_sums[lane] = ws;
    }
    __syncthreads();
    int excl  = inc - v + ((w > 0) ? warp_sums[w - 1] : 0);
    int total = warp_sums[7];

    if (t == 0) {
        if (b == 0) {
            atomicExch(&g_scan_pkt[0], (2ULL << 62) | (unsigned)total);
            s_base = 0;
        } else {
            atomicExch(&g_scan_pkt[b], (1ULL << 62) | (unsigned)total);
            int run = 0;
            int j = b - 1;
            while (true) {
                unsigned long long p;
                while (((p = atomicAdd(&g_scan_pkt[j], 0ULL)) >> 62) == 0) {}
                run += (int)(p & 0xFFFFFFFFULL);
                if ((p >> 62) == 2ULL) break;
                j--;
            }
            atomicExch(&g_scan_pkt[b], (2ULL << 62) | (unsigned)(run + total));
            s_base = run;
        }
    }
    __syncthreads();
    int base = s_base;
    if (i < N_NODES) g_off[i] = base + excl;
    if (i == N_NODES - 1) g_off[N_NODES] = N_EDGES;
}

// ---------------------------------------------------------------------------
// Scatter: atomic-free, position = off[row] + rank
// ---------------------------------------------------------------------------
__global__ __launch_bounds__(256)
void k_scatter(const int*   __restrict__ edge_row,
               const int*   __restrict__ edge_col,
               const float* __restrict__ edge_val) {
    int e = blockIdx.x * blockDim.x + threadIdx.x;
    if (e < N_EDGES) {
        int r = edge_row[e];
        int p = g_off[r] + g_rank[e];
        g_cv[p] = make_int2(edge_col[e], __float_as_int(edge_val[e]));
    }
}

// ---------------------------------------------------------------------------
// GEMM  Y[m,n] = sum_k X[m,k]*W[n,k]  (fp16 MMA, fp32 acc) — R6-proven shape.
// CTA 128x128, BK=32, 8 warps 4(M) x 2(N), 256 threads, 2 CTAs/SM.
// ---------------------------------------------------------------------------
#define BM 128
#define BN 128
#define BK 32
#define LDS_K 40

__device__ __forceinline__ void mma_f16(float* c, const uint32_t* a, const uint32_t* b) {
    asm volatile(
        "mma.sync.aligned.m16n8k16.row.col.f32.f16.f16.f32 "
        "{%0,%1,%2,%3}, {%4,%5,%6,%7}, {%8,%9}, {%0,%1,%2,%3};"
        : "+f"(c[0]), "+f"(c[1]), "+f"(c[2]), "+f"(c[3])
        : "r"(a[0]), "r"(a[1]), "r"(a[2]), "r"(a[3]), "r"(b[0]), "r"(b[1]));
}

__global__ __launch_bounds__(256, 2)
void gemm_kernel(const float* __restrict__ X) {
    __shared__ __half As[BM][LDS_K];
    __shared__ __half Ws[BN][LDS_K];

    const int t    = threadIdx.x;
    const int lane = t & 31;
    const int wid  = t >> 5;
    const int wm   = wid & 3;
    const int wn   = wid >> 2;
    const int g    = lane >> 2;
    const int tid4 = lane & 3;

    const int m0 = blockIdx.x * BM;
    const int n0 = blockIdx.y * BN;

    float acc[2][8][4];
#pragma unroll
    for (int i = 0; i < 2; i++)
#pragma unroll
        for (int j = 0; j < 8; j++)
#pragma unroll
            for (int k = 0; k < 4; k++) acc[i][j][k] = 0.f;

    for (int k0 = 0; k0 < F_DIM; k0 += BK) {
        // stage X tile (fp32 -> fp16), rows >= N_NODES zero-filled
#pragma unroll
        for (int i = 0; i < 4; i++) {
            int idx = t + i * 256;       // 0..1023
            int row = idx >> 3;          // 0..127
            int c4  = idx & 7;           // 0..7
            int m   = m0 + row;
            float4 v = make_float4(0.f, 0.f, 0.f, 0.f);
            if (m < N_NODES)
                v = *reinterpret_cast<const float4*>(X + (size_t)m * F_DIM + k0 + c4 * 4);
            __half2 h0 = __floats2half2_rn(v.x, v.y);
            __half2 h1 = __floats2half2_rn(v.z, v.w);
            uint2 u;
            u.x = *reinterpret_cast<uint32_t*>(&h0);
            u.y = *reinterpret_cast<uint32_t*>(&h1);
            *reinterpret_cast<uint2*>(&As[row][c4 * 4]) = u;
        }
        // stage W tile: straight 16B copies of pre-converted fp16
#pragma unroll
        for (int i = 0; i < 2; i++) {
            int idx = t + i * 256;       // 0..511
            int row = idx >> 2;          // 0..127
            int c8  = idx & 3;
            size_t goff = (size_t)(n0 + row) * F_DIM + k0 + c8 * 8;
            uint4 vh = *reinterpret_cast<const uint4*>(g_wh + goff);
            *reinterpret_cast<uint4*>(&Ws[row][c8 * 8]) = vh;
        }
        __syncthreads();

#pragma unroll
        for (int ks = 0; ks < 2; ks++) {
            int kb = ks * 16;
            uint32_t a[2][4];
#pragma unroll
            for (int mi = 0; mi < 2; mi++) {
                int r = wm * 32 + mi * 16;
                a[mi][0] = *reinterpret_cast<const uint32_t*>(&As[r + g    ][kb + 2 * tid4]);
                a[mi][1] = *reinterpret_cast<const uint32_t*>(&As[r + g + 8][kb + 2 * tid4]);
                a[mi][2] = *reinterpret_cast<const uint32_t*>(&As[r + g    ][kb + 2 * tid4 + 8]);
                a[mi][3] = *reinterpret_cast<const uint32_t*>(&As[r + g + 8][kb + 2 * tid4 + 8]);
            }
            uint32_t b[8][2];
#pragma unroll
            for (int ni = 0; ni < 8; ni++) {
                int n = wn * 64 + ni * 8 + g;
                b[ni][0] = *reinterpret_cast<const uint32_t*>(&Ws[n][kb + 2 * tid4]);
                b[ni][1] = *reinterpret_cast<const uint32_t*>(&Ws[n][kb + 2 * tid4 + 8]);
            }
#pragma unroll
            for (int mi = 0; mi < 2; mi++)
#pragma unroll
                for (int ni = 0; ni < 8; ni++)
                    mma_f16(acc[mi][ni], a[mi], b[ni]);
        }
        __syncthreads();
    }

    // store Y as fp16
#pragma unroll
    for (int mi = 0; mi < 2; mi++) {
        int r_base = m0 + wm * 32 + mi * 16;
#pragma unroll
        for (int ni = 0; ni < 8; ni++) {
            int col = n0 + wn * 64 + ni * 8 + 2 * tid4;
            int r0 = r_base + g;
            int r1 = r_base + g + 8;
            if (r0 < N_NODES) {
                __half2 h = __floats2half2_rn(acc[mi][ni][0], acc[mi][ni][1]);
                *reinterpret_cast<__half2*>(g_yh + (size_t)r0 * F_DIM + col) = h;
            }
            if (r1 < N_NODES) {
                __half2 h = __floats2half2_rn(acc[mi][ni][2], acc[mi][ni][3]);
                *reinterpret_cast<__half2*>(g_yh + (size_t)r1 * F_DIM + col) = h;
            }
        }
    }
}

// ---------------------------------------------------------------------------
// Gather: out[r] = sum_e val_e * Y[col_e] + b.  One warp per row.
// Packed f32x2 FMA (sm_103a FFMA2): 4 fma.rn.f32x2 per edge per lane.
// ---------------------------------------------------------------------------
__device__ __forceinline__ void fma8_x2(unsigned long long* acc, uint4 u,
                                        unsigned long long v2) {
    const __half2* h = reinterpret_cast<const __half2*>(&u);
#pragma unroll
    for (int q = 0; q < 4; q++) {
        float2 f = __half22float2(h[q]);
        unsigned long long fu;
        asm("mov.b64 %0, {%1, %2};" : "=l"(fu) : "f"(f.x), "f"(f.y));
        asm("fma.rn.f32x2 %0, %1, %2, %0;" : "+l"(acc[q]) : "l"(fu), "l"(v2));
    }
}

__global__ __launch_bounds__(256, 6)
void k_gather(const float* __restrict__ bias, float* __restrict__ out) {
    int r    = (blockIdx.x * blockDim.x + threadIdx.x) >> 5;
    int lane = threadIdx.x & 31;
    if (r >= N_NODES) return;

    unsigned long long acc[4];
#pragma unroll
    for (int q = 0; q < 4; q++) acc[q] = 0ULL;

    int start = g_off[r];
    int end   = g_off[r + 1];

    for (int base = start; base < end; base += 32) {
        int n = min(32, end - base);
        int   col = 0;
        float val = 0.f;
        if (lane < n) {
            int2 cv = __ldg(&g_cv[base + lane]);
            col = cv.x;
            val = __int_as_float(cv.y);
        }
        int j = 0;
        for (; j + 4 <= n; j += 4) {
            int   c0 = __shfl_sync(0xffffffffu, col, j);
            int   c1 = __shfl_sync(0xffffffffu, col, j + 1);
            int   c2 = __shfl_sync(0xffffffffu, col, j + 2);
            int   c3 = __shfl_sync(0xffffffffu, col, j + 3);
            float v0 = __shfl_sync(0xffffffffu, val, j);
            float v1 = __shfl_sync(0xffffffffu, val, j + 1);
            float v2 = __shfl_sync(0xffffffffu, val, j + 2);
            float v3 = __shfl_sync(0xffffffffu, val, j + 3);
            uint4 u0 = __ldg(reinterpret_cast<const uint4*>(g_yh + (size_t)c0 * F_DIM) + lane);
            uint4 u1 = __ldg(reinterpret_cast<const uint4*>(g_yh + (size_t)c1 * F_DIM) + lane);
            uint4 u2 = __ldg(reinterpret_cast<const uint4*>(g_yh + (size_t)c2 * F_DIM) + lane);
            uint4 u3 = __ldg(reinterpret_cast<const uint4*>(g_yh + (size_t)c3 * F_DIM) + lane);
            unsigned long long p0, p1, p2, p3;
            asm("mov.b64 %0, {%1, %1};" : "=l"(p0) : "f"(v0));
            asm("mov.b64 %0, {%1, %1};" : "=l"(p1) : "f"(v1));
            asm("mov.b64 %0, {%1, %1};" : "=l"(p2) : "f"(v2));
            asm("mov.b64 %0, {%1, %1};" : "=l"(p3) : "f"(v3));
            fma8_x2(acc, u0, p0);
            fma8_x2(acc, u1, p1);
            fma8_x2(acc, u2, p2);
            fma8_x2(acc, u3, p3);
        }
        for (; j < n; j++) {
            int   c = __shfl_sync(0xffffffffu, col, j);
            float v = __shfl_sync(0xffffffffu, val, j);
            uint4 u = __ldg(reinterpret_cast<const uint4*>(g_yh + (size_t)c * F_DIM) + lane);
            unsigned long long p;
            asm("mov.b64 %0, {%1, %1};" : "=l"(p) : "f"(v));
            fma8_x2(acc, u, p);
        }
    }

    // unpack, add bias, store
    float a[8];
#pragma unroll
    for (int q = 0; q < 4; q++) {
        float lo, hi;
        asm("mov.b64 {%0, %1}, %2;" : "=f"(lo), "=f"(hi) : "l"(acc[q]));
        a[2 * q]     = lo;
        a[2 * q + 1] = hi;
    }
    const float4* bp = reinterpret_cast<const float4*>(bias + lane * 8);
    float4 b0 = __ldg(bp);
    float4 b1 = __ldg(bp + 1);
    float4 o0 = make_float4(a[0] + b0.x, a[1] + b0.y, a[2] + b0.z, a[3] + b0.w);
    float4 o1 = make_float4(a[4] + b1.x, a[5] + b1.y, a[6] + b1.z, a[7] + b1.w);
    float4* orow = reinterpret_cast<float4*>(out + (size_t)r * F_DIM + lane * 8);
    orow[0] = o0;
    orow[1] = o1;
}

// ---------------------------------------------------------------------------
// Launch
// ---------------------------------------------------------------------------
extern "C" void kernel_launch(void* const* d_in, const int* in_sizes, int n_in,
                              void* d_out, int out_size) {
    const float* x        = (const float*)d_in[0];
    const int*   edge_row = (const int*)  d_in[1];
    const int*   edge_col = (const int*)  d_in[2];
    const float* edge_val = (const float*)d_in[3];
    const float* W        = (const float*)d_in[4];
    const float* b        = (const float*)d_in[5];
    float*       out      = (float*)d_out;

    void* cnt_ptr = nullptr;
    cudaGetSymbolAddress(&cnt_ptr, g_cnt);
    cudaMemsetAsync(cnt_ptr, 0, N_NODES * sizeof(int));
    void* pkt_ptr = nullptr;
    cudaGetSymbolAddress(&pkt_ptr, g_scan_pkt);
    cudaMemsetAsync(pkt_ptr, 0, SCAN_NB * sizeof(unsigned long long));

    // A: hist (+rank) | prep_w
    k_fused_a<<<F1_BLOCKS, 256>>>(edge_row, W);
    // B: scan
    k_scan_fused<<<SCAN_NB, SCAN_B>>>();
    // C: scatter (atomic-free)
    k_scatter<<<(N_EDGES + 255) / 256, 256>>>(edge_row, edge_col, edge_val);
    // D: GEMM
    dim3 grid(PAD_M / BM, F_DIM / BN);   // 391 x 2
    gemm_kernel<<<grid, 256>>>(x);
    // E: gather
    k_gather<<<(N_NODES * 32 + 255) / 256, 256>>>(b, out);
}